// round 7
// baseline (speedup 1.0000x reference)
#include <cuda_runtime.h>
#include <cuda_fp16.h>
#include <cstdint>
#include <math.h>

#define BATCH 4
#define CDIM  2048
#define EDIM  1024

// ------------------------- scratch (__device__ globals) ---------------------
__device__ __half g_xh  [(size_t)BATCH * CDIM * EDIM];  // x    [b,C,E] fp16
__device__ __half g_xTh [(size_t)BATCH * CDIM * EDIM];  // xT   [b,E,C] fp16
__device__ __half g_yh  [(size_t)BATCH * CDIM * EDIM];  // y    [b,C,E] fp16
__device__ __half g_zh  [(size_t)BATCH * CDIM * EDIM];  // z    [b,C,E] fp16
__device__ __half g_vxTh[(size_t)BATCH * CDIM * EDIM];  // vxT  [b,E,C] fp16
__device__ __half g_fwh [(size_t)EDIM * EDIM];          // fp16 weights
__device__ __half g_vwh [(size_t)EDIM * EDIM];
__device__ __half g_awh [(size_t)CDIM * CDIM];
__device__ __half g_lgh  [(size_t)BATCH * CDIM * CDIM]; // attn logits*scale f16
__device__ __half g_attnh[(size_t)BATCH * CDIM * CDIM]; // attn weights fp16
__device__ int    g_mask_mode;                          // 0=u8, 1=i32, 2=f32

// ------------------------- helpers ------------------------------------------
__device__ __forceinline__ uint32_t smem_u32(const void* p) {
    uint32_t a;
    asm("{ .reg .u64 t; cvta.to.shared.u64 t, %1; cvt.u32.u64 %0, t; }"
        : "=r"(a) : "l"(p));
    return a;
}
__device__ __forceinline__ void ldm_x4(unsigned* r, uint32_t addr) {
    asm volatile("ldmatrix.sync.aligned.m8n8.x4.shared.b16 {%0,%1,%2,%3}, [%4];"
                 : "=r"(r[0]), "=r"(r[1]), "=r"(r[2]), "=r"(r[3]) : "r"(addr));
}
__device__ __forceinline__ void mma_f16(float* c, const unsigned* a, const unsigned* b) {
    asm volatile(
        "mma.sync.aligned.m16n8k16.row.col.f32.f16.f16.f32 "
        "{%0,%1,%2,%3}, {%4,%5,%6,%7}, {%8,%9}, {%0,%1,%2,%3};"
        : "+f"(c[0]), "+f"(c[1]), "+f"(c[2]), "+f"(c[3])
        : "r"(a[0]), "r"(a[1]), "r"(a[2]), "r"(a[3]), "r"(b[0]), "r"(b[1]));
}
#define CP_COMMIT() asm volatile("cp.async.commit_group;" ::: "memory")
#define CP_WAIT(n)  asm volatile("cp.async.wait_group %0;" :: "n"(n) : "memory")

// ------------------------- mask-mode detection ------------------------------
__global__ void detect_mask_kernel(const unsigned int* __restrict__ w, int nwords)
{
    __shared__ int sawFloat, sawMulti;
    if (threadIdx.x == 0) { sawFloat = 0; sawMulti = 0; }
    __syncthreads();
    for (int i = threadIdx.x; i < nwords; i += blockDim.x) {
        unsigned int v = w[i];
        if (v == 0x3F800000u) atomicOr(&sawFloat, 1);
        else if (v > 1u)      atomicOr(&sawMulti, 1);
    }
    __syncthreads();
    if (threadIdx.x == 0)
        g_mask_mode = sawFloat ? 2 : (sawMulti ? 0 : 1);
}

// ------------------------- f32 -> f16 conversion ----------------------------
__global__ void cvt_kernel(const float4* __restrict__ in, __half2* __restrict__ out, int n4)
{
    int i = blockIdx.x * 256 + threadIdx.x;
    if (i < n4) {
        float4 v = in[i];
        out[2 * i]     = __floats2half2_rn(v.x, v.y);
        out[2 * i + 1] = __floats2half2_rn(v.z, v.w);
    }
}

// --------------- transpose+cvt: x f32 -> xh [C,E] f16 AND xTh [E,C] f16 -----
__global__ void transpose_dual_kernel(const float* __restrict__ in,
                                      __half* __restrict__ xh,
                                      __half* __restrict__ xTh)
{
    __shared__ float t[32][33];
    const long long boff = (long long)blockIdx.z * CDIM * EDIM;
    const int e0 = blockIdx.x * 32, c0 = blockIdx.y * 32;
    const int tx = threadIdx.x, ty = threadIdx.y;   // (32, 8)
    #pragma unroll
    for (int j = 0; j < 32; j += 8) {
        float v = in[boff + (long long)(c0 + ty + j) * EDIM + e0 + tx];
        t[ty + j][tx] = v;
        xh[boff + (long long)(c0 + ty + j) * EDIM + e0 + tx] = __float2half_rn(v);
    }
    __syncthreads();
    #pragma unroll
    for (int j = 0; j < 32; j += 8)
        xTh[boff + (long long)(e0 + ty + j) * CDIM + c0 + tx] = __float2half_rn(t[tx][ty + j]);
}

// ---------------------------------------------------------------------------
// FP16 mma.sync NT GEMM (multi-op): C[m,n] = sum_k A[m,k]*B[n,k] (+f32 bias)
// CTA tile 256x128, 256 threads, 8 warps (4x2, warp tile 64x64),
// K-chunk 64 halves (128B rows, XOR swizzle), cp.async 4-stage pipeline,
// ldmatrix.x4 fragments. Op = blockIdx.z>>2, batch = blockIdx.z&3.
// biasMode: 0=none, 1=col, 2=row. outMode: 0=f16, 1=f32, 2=f16*SCALE.
// ---------------------------------------------------------------------------
#define STAGE_BYTES 49152                 // A 32KB + B 16KB
#define NSTAGE 4
#define SMEM_DYN   (NSTAGE * STAGE_BYTES) // 192 KB

#define ATT_SCALE 0.022097086912079612f   // 1/sqrt(2048)

struct GOp {
    const __half* A; const __half* B; const float* bias; void* C;
    long long sA, sB, sC;
    int K, lda, ldb, ldc, biasMode, outMode, nbx;
};
struct GParams { GOp op[3]; };

// A tile: 256 rows x 128B, B tile: 128 rows x 128B
__device__ __forceinline__ void cp_tile_a(uint32_t base, const __half* g, int ld, int tid)
{
    #pragma unroll
    for (int l = 0; l < 8; l++) {
        int idx = tid + l * 256;          // 0..2047
        int r  = idx >> 3;                // 0..255
        int cb = (idx & 7) << 4;
        uint32_t dst = base + r * 128 + (cb ^ ((r & 7) << 4));
        const __half* src = g + (long long)r * ld + (cb >> 1);
        asm volatile("cp.async.cg.shared.global [%0], [%1], 16;"
                     :: "r"(dst), "l"(src) : "memory");
    }
}
__device__ __forceinline__ void cp_tile_b(uint32_t base, const __half* g, int ld, int tid)
{
    #pragma unroll
    for (int l = 0; l < 4; l++) {
        int idx = tid + l * 256;          // 0..1023
        int r  = idx >> 3;                // 0..127
        int cb = (idx & 7) << 4;
        uint32_t dst = base + r * 128 + (cb ^ ((r & 7) << 4));
        const __half* src = g + (long long)r * ld + (cb >> 1);
        asm volatile("cp.async.cg.shared.global [%0], [%1], 16;"
                     :: "r"(dst), "l"(src) : "memory");
    }
}

__global__ void __launch_bounds__(256, 1)
gemm_any(GParams P)
{
    extern __shared__ char sm[];
    const uint32_t smem0 = smem_u32(sm);

    const GOp o = P.op[blockIdx.z >> 2];
    const int batch = blockIdx.z & 3;
    const int bx = blockIdx.x % o.nbx;
    const int by = blockIdx.x / o.nbx;

    const int tid  = threadIdx.x;
    const int lane = tid & 31;
    const int wid  = tid >> 5;
    const int wm   = (wid & 3) * 64;      // 4 warps along M (256)
    const int wn   = (wid >> 2) * 64;     // 2 warps along N (128)
    const int g    = lane >> 2;
    const int tc   = lane & 3;

    const __half* A = o.A + (long long)batch * o.sA + (long long)(by * 256) * o.lda;
    const __half* B = o.B + (long long)batch * o.sB + (long long)(bx * 128) * o.ldb;

    // ldmatrix per-lane address components
    const int arow = (lane & 15);
    const int akx  = (lane >> 4) << 4;
    const int brow = (lane & 7) + ((lane >> 4) & 1) * 8;
    const int bkx  = ((lane >> 3) & 1) << 4;

    float acc[4][8][4];
    #pragma unroll
    for (int i = 0; i < 4; i++)
        #pragma unroll
        for (int j = 0; j < 8; j++)
            #pragma unroll
            for (int k = 0; k < 4; k++) acc[i][j][k] = 0.f;

    const int nk = o.K >> 6;              // K-chunks of 64 (>= 16 here)

    #pragma unroll
    for (int p = 0; p < 3; p++) {         // prefetch depth 3
        const uint32_t st = smem0 + p * STAGE_BYTES;
        cp_tile_a(st,         A + p * 64, o.lda, tid);
        cp_tile_b(st + 32768, B + p * 64, o.ldb, tid);
        CP_COMMIT();
    }

    int s = 0;
    for (int i = 0; i < nk; i++) {
        if (i + 2 < nk)      CP_WAIT(2);
        else if (i + 1 < nk) CP_WAIT(1);
        else                 CP_WAIT(0);
        __syncthreads();
        if (i + 3 < nk) {
            int s3 = s + 3; if (s3 >= NSTAGE) s3 -= NSTAGE;
            const uint32_t nb = smem0 + s3 * STAGE_BYTES;
            cp_tile_a(nb,         A + (i + 3) * 64, o.lda, tid);
            cp_tile_b(nb + 32768, B + (i + 3) * 64, o.ldb, tid);
            CP_COMMIT();
        }

        const uint32_t As = smem0 + s * STAGE_BYTES;
        const uint32_t Bs = As + 32768;
        #pragma unroll
        for (int ks = 0; ks < 4; ks++) {
            const int kb = ks * 32;
            unsigned a[4][4], b[4][4];
            #pragma unroll
            for (int mf = 0; mf < 4; mf++) {
                int r = wm + mf * 16 + arow;
                ldm_x4(a[mf], As + r * 128 + ((kb + akx) ^ ((r & 7) << 4)));
            }
            #pragma unroll
            for (int p = 0; p < 4; p++) {
                int r = wn + p * 16 + brow;
                ldm_x4(b[p], Bs + r * 128 + ((kb + bkx) ^ ((r & 7) << 4)));
            }
            #pragma unroll
            for (int mf = 0; mf < 4; mf++)
                #pragma unroll
                for (int p = 0; p < 4; p++) {
                    mma_f16(acc[mf][2 * p],     a[mf], &b[p][0]);
                    mma_f16(acc[mf][2 * p + 1], a[mf], &b[p][2]);
                }
        }
        if (++s == NSTAGE) s = 0;
    }

    // ------------------------- epilogue -------------------------------------
    #pragma unroll
    for (int mf = 0; mf < 4; mf++) {
        #pragma unroll
        for (int nf = 0; nf < 8; nf++) {
            const int r0 = by * 256 + wm + mf * 16 + g;
            const int c  = bx * 128 + wn + nf * 8 + 2 * tc;
            float v0 = acc[mf][nf][0], v1 = acc[mf][nf][1];
            float v2 = acc[mf][nf][2], v3 = acc[mf][nf][3];
            if (o.biasMode == 1) {
                const float b0 = o.bias[c], b1 = o.bias[c + 1];
                v0 += b0; v1 += b1; v2 += b0; v3 += b1;
            } else if (o.biasMode == 2) {
                const float br0 = o.bias[r0], br1 = o.bias[r0 + 8];
                v0 += br0; v1 += br0; v2 += br1; v3 += br1;
            }
            if (o.outMode == 1) {
                float* Cb = (float*)o.C + (long long)batch * o.sC;
                *reinterpret_cast<float2*>(Cb + (long long)r0 * o.ldc + c)       = make_float2(v0, v1);
                *reinterpret_cast<float2*>(Cb + (long long)(r0 + 8) * o.ldc + c) = make_float2(v2, v3);
            } else {
                const float scl = (o.outMode == 2) ? ATT_SCALE : 1.f;
                __half* Cb = (__half*)o.C + (long long)batch * o.sC;
                *reinterpret_cast<__half2*>(Cb + (long long)r0 * o.ldc + c)       = __floats2half2_rn(v0 * scl, v1 * scl);
                *reinterpret_cast<__half2*>(Cb + (long long)(r0 + 8) * o.ldc + c) = __floats2half2_rn(v2 * scl, v3 * scl);
            }
        }
    }
}

// ------------------------- masked softmax over k -----------------------------
__global__ void softmax_kernel(const __half* __restrict__ lg,
                               __half* __restrict__ attn_h,
                               const void* __restrict__ mask_raw)
{
    const long long row = blockIdx.x;
    const __half* p = lg + row * CDIM;
    __half* po = attn_h + row * CDIM;
    const int tid = threadIdx.x;
    const int mode = g_mask_mode;

    const unsigned char* mb = (const unsigned char*)mask_raw + row * CDIM;
    const int*           mi = (const int*)mask_raw          + row * CDIM;
    const float*         mf = (const float*)mask_raw        + row * CDIM;

    float v[8];
    bool mm[8];
    float lmax = -INFINITY;
    #pragma unroll
    for (int i = 0; i < 8; i++) {
        int e = tid + i * 256;
        bool masked;
        if      (mode == 0) masked = (mb[e] != 0);
        else if (mode == 1) masked = (mi[e] != 0);
        else                masked = (mf[e] != 0.f);
        mm[i] = masked;
        float t = masked ? -INFINITY : __half2float(p[e]);
        v[i] = t;
        lmax = fmaxf(lmax, t);
    }

    __shared__ float red[256];
    red[tid] = lmax; __syncthreads();
    #pragma unroll
    for (int s = 128; s > 0; s >>= 1) {
        if (tid < s) red[tid] = fmaxf(red[tid], red[tid + s]);
        __syncthreads();
    }
    const float rmax = red[0];
    __syncthreads();

    float lsum = 0.f;
    #pragma unroll
    for (int i = 0; i < 8; i++) {
        v[i] = mm[i] ? 0.f : __expf(v[i] - rmax);
        lsum += v[i];
    }
    red[tid] = lsum; __syncthreads();
    #pragma unroll
    for (int s = 128; s > 0; s >>= 1) {
        if (tid < s) red[tid] += red[tid + s];
        __syncthreads();
    }
    const float inv = 1.f / red[0];
    #pragma unroll
    for (int i = 0; i < 8; i++)
        po[tid + i * 256] = __float2half_rn(v[i] * inv);
}

// ---------------------------------------------------------------------------
extern "C" void kernel_launch(void* const* d_in, const int* in_sizes, int n_in,
                              void* d_out, int out_size)
{
    const float* x     = (const float*)d_in[0];   // [B,C,E]
    const float* fc_w  = (const float*)d_in[1];   // [E,E]
    const float* fc_b  = (const float*)d_in[2];   // [E]
    const float* alt_w = (const float*)d_in[3];   // [C,C]
    const float* alt_b = (const float*)d_in[4];   // [C]
    const float* v_w   = (const float*)d_in[5];   // [E,E]
    const float* v_b   = (const float*)d_in[6];   // [E]
    const void*  mask  = d_in[7];                 // [B,C,C] bool (encoding detected)
    float* out = (float*)d_out;                   // [B,C,E]

    __half *xh, *xTh, *yh, *zh, *vxTh, *fwh, *vwh, *awh, *lgh, *attnh;
    cudaGetSymbolAddress((void**)&xh,    g_xh);
    cudaGetSymbolAddress((void**)&xTh,   g_xTh);
    cudaGetSymbolAddress((void**)&yh,    g_yh);
    cudaGetSymbolAddress((void**)&zh,    g_zh);
    cudaGetSymbolAddress((void**)&vxTh,  g_vxTh);
    cudaGetSymbolAddress((void**)&fwh,   g_fwh);
    cudaGetSymbolAddress((void**)&vwh,   g_vwh);
    cudaGetSymbolAddress((void**)&awh,   g_awh);
    cudaGetSymbolAddress((void**)&lgh,   g_lgh);
    cudaGetSymbolAddress((void**)&attnh, g_attnh);

    cudaFuncSetAttribute(gemm_any, cudaFuncAttributeMaxDynamicSharedMemorySize, SMEM_DYN);

    const long long sCE = (long long)CDIM * EDIM;
    const long long sCC = (long long)CDIM * CDIM;

    // 0) mask encoding + fp16 conversions
    detect_mask_kernel<<<1, 256>>>((const unsigned int*)mask, 16384);
    {
        int n4 = (EDIM * EDIM) / 4;
        cvt_kernel<<<(n4 + 255) / 256, 256>>>((const float4*)fc_w, (__half2*)fwh, n4);
        cvt_kernel<<<(n4 + 255) / 256, 256>>>((const float4*)v_w,  (__half2*)vwh, n4);
        n4 = (CDIM * CDIM) / 4;
        cvt_kernel<<<(n4 + 255) / 256, 256>>>((const float4*)alt_w, (__half2*)awh, n4);
    }
    transpose_dual_kernel<<<dim3(EDIM / 32, CDIM / 32, BATCH), dim3(32, 8)>>>(x, xh, xTh);

    // 1-3) merged independent GEMMs (one launch, 768 CTAs)
    //   g1: y[c,f]   = x[c,e]*fc_w[f,e] + fc_b[f]    M=C,N=E,K=E (col bias)
    //   g2: vxT[f,k] = v_w[f,e]*x[k,e] + v_b[f]      M=E,N=C,K=E (row bias)
    //   g3: z[k,e]   = alt_w[k,c]*xT[e,c] + alt_b[k] M=C,N=E,K=C (row bias)
    {
        GParams P;
        P.op[0] = { xh,  fwh, fc_b,  yh,   sCE, 0,   sCE, EDIM, EDIM, EDIM, EDIM, 1, 0, EDIM / 128 };
        P.op[1] = { vwh, xh,  v_b,   vxTh, 0,   sCE, sCE, EDIM, EDIM, EDIM, CDIM, 2, 0, CDIM / 128 };
        P.op[2] = { awh, xTh, alt_b, zh,   0,   sCE, sCE, CDIM, CDIM, CDIM, EDIM, 2, 0, EDIM / 128 };
        gemm_any<<<dim3(64, 1, 12), 256, SMEM_DYN>>>(P);
    }

    // 4) logits[c,k] = (sum_e y[c,e]*z[k,e]) * 1/sqrt(C)  -> f16
    {
        GParams P;
        P.op[0] = { yh, zh, nullptr, lgh, sCE, sCE, sCC, EDIM, EDIM, EDIM, CDIM, 0, 2, CDIM / 128 };
        gemm_any<<<dim3(128, 1, 4), 256, SMEM_DYN>>>(P);
    }

    // 5) masked softmax over k -> fp16 weights
    softmax_kernel<<<BATCH * CDIM, 256>>>(lgh, attnh, mask);

    // 6) out[c,e] = sum_k attn[c,k]*vxT[e,k]  (f32 out)
    {
        GParams P;
        P.op[0] = { attnh, vxTh, nullptr, out, sCC, sCE, sCE, CDIM, CDIM, CDIM, EDIM, 0, 1, EDIM / 128 };
        gemm_any<<<dim3(64, 1, 4), 256, SMEM_DYN>>>(P);
    }
}

// round 8
// speedup vs baseline: 1.1092x; 1.1092x over previous
#include <cuda_runtime.h>
#include <cuda_fp16.h>
#include <cstdint>
#include <math.h>

#define BATCH 4
#define CDIM  2048
#define EDIM  1024

// ------------------------- scratch (__device__ globals) ---------------------
__device__ __half g_xh  [(size_t)BATCH * CDIM * EDIM];  // x    [b,C,E] fp16
__device__ __half g_xTh [(size_t)BATCH * CDIM * EDIM];  // xT   [b,E,C] fp16
__device__ __half g_yh  [(size_t)BATCH * CDIM * EDIM];  // y    [b,C,E] fp16
__device__ __half g_zh  [(size_t)BATCH * CDIM * EDIM];  // z    [b,C,E] fp16
__device__ __half g_vxTh[(size_t)BATCH * CDIM * EDIM];  // vxT  [b,E,C] fp16
__device__ __half g_fwh [(size_t)EDIM * EDIM];          // fp16 weights
__device__ __half g_vwh [(size_t)EDIM * EDIM];
__device__ __half g_awh [(size_t)CDIM * CDIM];
__device__ __half g_lgh  [(size_t)BATCH * CDIM * CDIM]; // attn logits*scale f16
__device__ __half g_attnh[(size_t)BATCH * CDIM * CDIM]; // attn weights fp16
__device__ int    g_mask_mode;                          // 0=u8, 1=i32, 2=f32

// ------------------------- helpers ------------------------------------------
__device__ __forceinline__ uint32_t smem_u32(const void* p) {
    uint32_t a;
    asm("{ .reg .u64 t; cvta.to.shared.u64 t, %1; cvt.u32.u64 %0, t; }"
        : "=r"(a) : "l"(p));
    return a;
}
__device__ __forceinline__ void ldm_x4(unsigned* r, uint32_t addr) {
    asm volatile("ldmatrix.sync.aligned.m8n8.x4.shared.b16 {%0,%1,%2,%3}, [%4];"
                 : "=r"(r[0]), "=r"(r[1]), "=r"(r[2]), "=r"(r[3]) : "r"(addr));
}
__device__ __forceinline__ void mma_f16(float* c, const unsigned* a, const unsigned* b) {
    asm volatile(
        "mma.sync.aligned.m16n8k16.row.col.f32.f16.f16.f32 "
        "{%0,%1,%2,%3}, {%4,%5,%6,%7}, {%8,%9}, {%0,%1,%2,%3};"
        : "+f"(c[0]), "+f"(c[1]), "+f"(c[2]), "+f"(c[3])
        : "r"(a[0]), "r"(a[1]), "r"(a[2]), "r"(a[3]), "r"(b[0]), "r"(b[1]));
}
#define CP_COMMIT() asm volatile("cp.async.commit_group;" ::: "memory")
#define CP_WAIT(n)  asm volatile("cp.async.wait_group %0;" :: "n"(n) : "memory")

// ------------------------- mask-mode detection ------------------------------
__global__ void detect_mask_kernel(const unsigned int* __restrict__ w, int nwords)
{
    __shared__ int sawFloat, sawMulti;
    if (threadIdx.x == 0) { sawFloat = 0; sawMulti = 0; }
    __syncthreads();
    for (int i = threadIdx.x; i < nwords; i += blockDim.x) {
        unsigned int v = w[i];
        if (v == 0x3F800000u) atomicOr(&sawFloat, 1);
        else if (v > 1u)      atomicOr(&sawMulti, 1);
    }
    __syncthreads();
    if (threadIdx.x == 0)
        g_mask_mode = sawFloat ? 2 : (sawMulti ? 0 : 1);
}

// ------------------------- f32 -> f16 conversion ----------------------------
__global__ void cvt_kernel(const float4* __restrict__ in, __half2* __restrict__ out, int n4)
{
    int i = blockIdx.x * 256 + threadIdx.x;
    if (i < n4) {
        float4 v = in[i];
        out[2 * i]     = __floats2half2_rn(v.x, v.y);
        out[2 * i + 1] = __floats2half2_rn(v.z, v.w);
    }
}

// --------------- transpose+cvt: x f32 -> xh [C,E] f16 AND xTh [E,C] f16 -----
__global__ void transpose_dual_kernel(const float* __restrict__ in,
                                      __half* __restrict__ xh,
                                      __half* __restrict__ xTh)
{
    __shared__ float t[32][33];
    const long long boff = (long long)blockIdx.z * CDIM * EDIM;
    const int e0 = blockIdx.x * 32, c0 = blockIdx.y * 32;
    const int tx = threadIdx.x, ty = threadIdx.y;   // (32, 8)
    #pragma unroll
    for (int j = 0; j < 32; j += 8) {
        float v = in[boff + (long long)(c0 + ty + j) * EDIM + e0 + tx];
        t[ty + j][tx] = v;
        xh[boff + (long long)(c0 + ty + j) * EDIM + e0 + tx] = __float2half_rn(v);
    }
    __syncthreads();
    #pragma unroll
    for (int j = 0; j < 32; j += 8)
        xTh[boff + (long long)(e0 + ty + j) * CDIM + c0 + tx] = __float2half_rn(t[tx][ty + j]);
}

// ---------------------------------------------------------------------------
// FP16 mma.sync NT GEMM (multi-op): C[m,n] = sum_k A[m,k]*B[n,k] (+f32 bias)
// Block tile 128x128, 128 threads, 4 warps (2x2, warp tile 64x64),
// K-chunk 64 halves (128B rows, XOR swizzle), cp.async 3-stage pipeline,
// ldmatrix.x4 fragments with one-step register double-buffering.
// Op = blockIdx.z>>2, batch = blockIdx.z&3.
// biasMode: 0=none, 1=col, 2=row. outMode: 0=f16, 1=f32, 2=f16*SCALE.
// ---------------------------------------------------------------------------
#define STAGE_BYTES 32768                 // A 16KB + B 16KB
#define NSTAGE 3
#define SMEM_DYN   (NSTAGE * STAGE_BYTES) // 96 KB

#define ATT_SCALE 0.022097086912079612f   // 1/sqrt(2048)

struct GOp {
    const __half* A; const __half* B; const float* bias; void* C;
    long long sA, sB, sC;
    int K, lda, ldb, ldc, biasMode, outMode, nbx;
};
struct GParams { GOp op[3]; };

__device__ __forceinline__ void cp_tile_h(uint32_t base, const __half* g, int ld, int tid)
{
    #pragma unroll
    for (int l = 0; l < 8; l++) {
        int idx = tid + l * 128;          // 0..1023
        int r  = idx >> 3;                // 0..127
        int cb = (idx & 7) << 4;          // byte col 0..112
        uint32_t dst = base + r * 128 + (cb ^ ((r & 7) << 4));
        const __half* src = g + (long long)r * ld + (cb >> 1);
        asm volatile("cp.async.cg.shared.global [%0], [%1], 16;"
                     :: "r"(dst), "l"(src) : "memory");
    }
}

__global__ void __launch_bounds__(128, 2)
gemm_any(GParams P)
{
    extern __shared__ char sm[];
    const uint32_t smem0 = smem_u32(sm);

    const GOp o = P.op[blockIdx.z >> 2];
    const int batch = blockIdx.z & 3;
    const int bx = blockIdx.x % o.nbx;
    const int by = blockIdx.x / o.nbx;

    const int tid  = threadIdx.x;
    const int lane = tid & 31;
    const int wid  = tid >> 5;
    const int wm   = (wid & 1) * 64;
    const int wn   = (wid >> 1) * 64;
    const int g    = lane >> 2;
    const int tc   = lane & 3;

    const __half* A = o.A + (long long)batch * o.sA + (long long)(by * 128) * o.lda;
    const __half* B = o.B + (long long)batch * o.sB + (long long)(bx * 128) * o.ldb;

    // ldmatrix per-lane address components
    const int arow = (lane & 15);
    const int akx  = (lane >> 4) << 4;
    const int brow = (lane & 7) + ((lane >> 4) & 1) * 8;
    const int bkx  = ((lane >> 3) & 1) << 4;

    float acc[4][8][4];
    #pragma unroll
    for (int i = 0; i < 4; i++)
        #pragma unroll
        for (int j = 0; j < 8; j++)
            #pragma unroll
            for (int k = 0; k < 4; k++) acc[i][j][k] = 0.f;

    const int nk = o.K >> 6;              // K-chunks of 64

    cp_tile_h(smem0,         A, o.lda, tid);
    cp_tile_h(smem0 + 16384, B, o.ldb, tid);
    CP_COMMIT();
    cp_tile_h(smem0 + STAGE_BYTES,         A + 64, o.lda, tid);
    cp_tile_h(smem0 + STAGE_BYTES + 16384, B + 64, o.ldb, tid);
    CP_COMMIT();

    int s = 0;
    for (int i = 0; i < nk; i++) {
        if (i + 1 < nk) CP_WAIT(1); else CP_WAIT(0);
        __syncthreads();
        if (i + 2 < nk) {
            int s2 = s + 2; if (s2 >= NSTAGE) s2 -= NSTAGE;
            const uint32_t nb = smem0 + s2 * STAGE_BYTES;
            cp_tile_h(nb,         A + (i + 2) * 64, o.lda, tid);
            cp_tile_h(nb + 16384, B + (i + 2) * 64, o.ldb, tid);
            CP_COMMIT();
        }

        const uint32_t As = smem0 + s * STAGE_BYTES;
        const uint32_t Bs = As + 16384;

        // --- fragment double-buffer: load ks+1 before mma of ks ---
        unsigned a0[4][4], b0[4][4], a1[4][4], b1[4][4];
        #pragma unroll
        for (int mf = 0; mf < 4; mf++) {
            int r = wm + mf * 16 + arow;
            ldm_x4(a0[mf], As + r * 128 + ((0 + akx) ^ ((r & 7) << 4)));
        }
        #pragma unroll
        for (int p = 0; p < 4; p++) {
            int r = wn + p * 16 + brow;
            ldm_x4(b0[p], Bs + r * 128 + ((0 + bkx) ^ ((r & 7) << 4)));
        }
        #pragma unroll
        for (int ks = 0; ks < 4; ks++) {
            unsigned (&ac)[4][4] = (ks & 1) ? a1 : a0;
            unsigned (&bc)[4][4] = (ks & 1) ? b1 : b0;
            unsigned (&an)[4][4] = (ks & 1) ? a0 : a1;
            unsigned (&bn)[4][4] = (ks & 1) ? b0 : b1;
            if (ks < 3) {
                const int kb = (ks + 1) * 32;
                #pragma unroll
                for (int mf = 0; mf < 4; mf++) {
                    int r = wm + mf * 16 + arow;
                    ldm_x4(an[mf], As + r * 128 + ((kb + akx) ^ ((r & 7) << 4)));
                }
                #pragma unroll
                for (int p = 0; p < 4; p++) {
                    int r = wn + p * 16 + brow;
                    ldm_x4(bn[p], Bs + r * 128 + ((kb + bkx) ^ ((r & 7) << 4)));
                }
            }
            #pragma unroll
            for (int mf = 0; mf < 4; mf++)
                #pragma unroll
                for (int p = 0; p < 4; p++) {
                    mma_f16(acc[mf][2 * p],     ac[mf], &bc[p][0]);
                    mma_f16(acc[mf][2 * p + 1], ac[mf], &bc[p][2]);
                }
        }
        if (++s == NSTAGE) s = 0;
    }

    // ------------------------- epilogue -------------------------------------
    #pragma unroll
    for (int mf = 0; mf < 4; mf++) {
        #pragma unroll
        for (int nf = 0; nf < 8; nf++) {
            const int r0 = by * 128 + wm + mf * 16 + g;
            const int c  = bx * 128 + wn + nf * 8 + 2 * tc;
            float v0 = acc[mf][nf][0], v1 = acc[mf][nf][1];
            float v2 = acc[mf][nf][2], v3 = acc[mf][nf][3];
            if (o.biasMode == 1) {
                const float b0 = o.bias[c], b1 = o.bias[c + 1];
                v0 += b0; v1 += b1; v2 += b0; v3 += b1;
            } else if (o.biasMode == 2) {
                const float br0 = o.bias[r0], br1 = o.bias[r0 + 8];
                v0 += br0; v1 += br0; v2 += br1; v3 += br1;
            }
            if (o.outMode == 1) {
                float* Cb = (float*)o.C + (long long)batch * o.sC;
                *reinterpret_cast<float2*>(Cb + (long long)r0 * o.ldc + c)       = make_float2(v0, v1);
                *reinterpret_cast<float2*>(Cb + (long long)(r0 + 8) * o.ldc + c) = make_float2(v2, v3);
            } else {
                const float scl = (o.outMode == 2) ? ATT_SCALE : 1.f;
                __half* Cb = (__half*)o.C + (long long)batch * o.sC;
                *reinterpret_cast<__half2*>(Cb + (long long)r0 * o.ldc + c)       = __floats2half2_rn(v0 * scl, v1 * scl);
                *reinterpret_cast<__half2*>(Cb + (long long)(r0 + 8) * o.ldc + c) = __floats2half2_rn(v2 * scl, v3 * scl);
            }
        }
    }
}

// ------------------------- masked softmax over k -----------------------------
__global__ void softmax_kernel(const __half* __restrict__ lg,
                               __half* __restrict__ attn_h,
                               const void* __restrict__ mask_raw)
{
    const long long row = blockIdx.x;
    const __half* p = lg + row * CDIM;
    __half* po = attn_h + row * CDIM;
    const int tid = threadIdx.x;
    const int mode = g_mask_mode;

    const unsigned char* mb = (const unsigned char*)mask_raw + row * CDIM;
    const int*           mi = (const int*)mask_raw          + row * CDIM;
    const float*         mf = (const float*)mask_raw        + row * CDIM;

    float v[8];
    bool mm[8];
    float lmax = -INFINITY;
    #pragma unroll
    for (int i = 0; i < 8; i++) {
        int e = tid + i * 256;
        bool masked;
        if      (mode == 0) masked = (mb[e] != 0);
        else if (mode == 1) masked = (mi[e] != 0);
        else                masked = (mf[e] != 0.f);
        mm[i] = masked;
        float t = masked ? -INFINITY : __half2float(p[e]);
        v[i] = t;
        lmax = fmaxf(lmax, t);
    }

    __shared__ float red[256];
    red[tid] = lmax; __syncthreads();
    #pragma unroll
    for (int s = 128; s > 0; s >>= 1) {
        if (tid < s) red[tid] = fmaxf(red[tid], red[tid + s]);
        __syncthreads();
    }
    const float rmax = red[0];
    __syncthreads();

    float lsum = 0.f;
    #pragma unroll
    for (int i = 0; i < 8; i++) {
        v[i] = mm[i] ? 0.f : __expf(v[i] - rmax);
        lsum += v[i];
    }
    red[tid] = lsum; __syncthreads();
    #pragma unroll
    for (int s = 128; s > 0; s >>= 1) {
        if (tid < s) red[tid] += red[tid + s];
        __syncthreads();
    }
    const float inv = 1.f / red[0];
    #pragma unroll
    for (int i = 0; i < 8; i++)
        po[tid + i * 256] = __float2half_rn(v[i] * inv);
}

// ---------------------------------------------------------------------------
extern "C" void kernel_launch(void* const* d_in, const int* in_sizes, int n_in,
                              void* d_out, int out_size)
{
    const float* x     = (const float*)d_in[0];   // [B,C,E]
    const float* fc_w  = (const float*)d_in[1];   // [E,E]
    const float* fc_b  = (const float*)d_in[2];   // [E]
    const float* alt_w = (const float*)d_in[3];   // [C,C]
    const float* alt_b = (const float*)d_in[4];   // [C]
    const float* v_w   = (const float*)d_in[5];   // [E,E]
    const float* v_b   = (const float*)d_in[6];   // [E]
    const void*  mask  = d_in[7];                 // [B,C,C] bool (encoding detected)
    float* out = (float*)d_out;                   // [B,C,E]

    __half *xh, *xTh, *yh, *zh, *vxTh, *fwh, *vwh, *awh, *lgh, *attnh;
    cudaGetSymbolAddress((void**)&xh,    g_xh);
    cudaGetSymbolAddress((void**)&xTh,   g_xTh);
    cudaGetSymbolAddress((void**)&yh,    g_yh);
    cudaGetSymbolAddress((void**)&zh,    g_zh);
    cudaGetSymbolAddress((void**)&vxTh,  g_vxTh);
    cudaGetSymbolAddress((void**)&fwh,   g_fwh);
    cudaGetSymbolAddress((void**)&vwh,   g_vwh);
    cudaGetSymbolAddress((void**)&awh,   g_awh);
    cudaGetSymbolAddress((void**)&lgh,   g_lgh);
    cudaGetSymbolAddress((void**)&attnh, g_attnh);

    cudaFuncSetAttribute(gemm_any, cudaFuncAttributeMaxDynamicSharedMemorySize, SMEM_DYN);

    const long long sCE = (long long)CDIM * EDIM;
    const long long sCC = (long long)CDIM * CDIM;

    // 0) mask encoding + fp16 conversions
    detect_mask_kernel<<<1, 256>>>((const unsigned int*)mask, 16384);
    {
        int n4 = (EDIM * EDIM) / 4;
        cvt_kernel<<<(n4 + 255) / 256, 256>>>((const float4*)fc_w, (__half2*)fwh, n4);
        cvt_kernel<<<(n4 + 255) / 256, 256>>>((const float4*)v_w,  (__half2*)vwh, n4);
        n4 = (CDIM * CDIM) / 4;
        cvt_kernel<<<(n4 + 255) / 256, 256>>>((const float4*)alt_w, (__half2*)awh, n4);
    }
    transpose_dual_kernel<<<dim3(EDIM / 32, CDIM / 32, BATCH), dim3(32, 8)>>>(x, xh, xTh);

    // 1-3) merged independent GEMMs (one launch, 1536 CTAs)
    {
        GParams P;
        P.op[0] = { xh,  fwh, fc_b,  yh,   sCE, 0,   sCE, EDIM, EDIM, EDIM, EDIM, 1, 0, EDIM / 128 };
        P.op[1] = { vwh, xh,  v_b,   vxTh, 0,   sCE, sCE, EDIM, EDIM, EDIM, CDIM, 2, 0, CDIM / 128 };
        P.op[2] = { awh, xTh, alt_b, zh,   0,   sCE, sCE, CDIM, CDIM, CDIM, EDIM, 2, 0, EDIM / 128 };
        gemm_any<<<dim3(128, 1, 12), 128, SMEM_DYN>>>(P);
    }

    // 4) logits[c,k] = (sum_e y[c,e]*z[k,e]) * 1/sqrt(C)  -> f16
    {
        GParams P;
        P.op[0] = { yh, zh, nullptr, lgh, sCE, sCE, sCC, EDIM, EDIM, EDIM, CDIM, 0, 2, CDIM / 128 };
        gemm_any<<<dim3(256, 1, 4), 128, SMEM_DYN>>>(P);
    }

    // 5) masked softmax over k -> fp16 weights
    softmax_kernel<<<BATCH * CDIM, 256>>>(lgh, attnh, mask);

    // 6) out[c,e] = sum_k attn[c,k]*vxT[e,k]  (f32 out)
    {
        GParams P;
        P.op[0] = { attnh, vxTh, nullptr, out, sCC, sCE, sCE, CDIM, CDIM, CDIM, EDIM, 0, 1, EDIM / 128 };
        gemm_any<<<dim3(128, 1, 4), 128, SMEM_DYN>>>(P);
    }
}